// round 13
// baseline (speedup 1.0000x reference)
#include <cuda_runtime.h>
#include <math.h>

#define Hh 512
#define Ww 512
#define Bb 16
#define HW (Hh * Ww)
#define TOT (Bb * HW)
#define LOSS_BLOCKS_PER_B 8
#define NLOSSBLK (Bb * LOSS_BLOCKS_PER_B)

// ---------------- device scratch (static: no allocations allowed) ----------------
__device__ float         g_d[TOT];        // pass1: shifted-domain rows; final: absolute dist
__device__ float         g_w[TOT];        // boundary-loss weight w = t(1-p)+(1-t)p
__device__ unsigned char g_bmask[TOT];    // bit0: boundary, bit1: (tgt==0)
__device__ double        g_focal_acc;
__device__ double        g_inter[Bb], g_sp[Bb], g_st[Bb];
__device__ double        g_wsum[Bb], g_s2[Bb];
__device__ float         g_dmax[Bb];
__device__ int           g_hasb[Bb], g_hasfg[Bb];

// ---------------- zero accumulators (graph replay: reset every launch) ----------------
__global__ void zero_kernel() {
    int t = threadIdx.x;
    if (t == 0) g_focal_acc = 0.0;
    if (t < Bb) {
        g_inter[t] = 0.0; g_sp[t] = 0.0; g_st[t] = 0.0;
        g_wsum[t] = 0.0; g_s2[t] = 0.0;
        g_hasb[t] = 0; g_hasfg[t] = 0;
    }
}

// ---------------- boundary bits + per-sample flags ----------------
__global__ void prep_kernel(const int* __restrict__ tgt) {
    int idx = blockIdx.x * blockDim.x + threadIdx.x;   // grid sized exactly TOT
    int b   = idx / HW;
    int rem = idx - b * HW;
    int i   = rem / Ww;
    int j   = rem - i * Ww;
    const int* tb = tgt + b * HW;

    int anyFg = 0, anyBg = 0;
    #pragma unroll
    for (int di = -1; di <= 1; di++) {
        int ii = i + di;
        if (ii < 0 || ii >= Hh) continue;   // OOB contributes 0 to both maxpools
        #pragma unroll
        for (int dj = -1; dj <= 1; dj++) {
            int jj = j + dj;
            if (jj < 0 || jj >= Ww) continue;
            int v = tb[ii * Ww + jj];
            anyFg |= (v != 0);
            anyBg |= (v == 0);
        }
    }
    int boundary = anyFg & anyBg;            // dil==1 && ero==0
    int fgc      = (tb[rem] != 0);
    g_bmask[idx] = (unsigned char)(boundary | ((fgc ^ 1) << 1));

    int ab = __syncthreads_or(boundary);     // block lies fully inside one sample
    int af = __syncthreads_or(fgc);
    if (threadIdx.x == 0) {
        if (ab) atomicOr(&g_hasb[b], 1);
        if (af) atomicOr(&g_hasfg[b], 1);
    }
}

// ---------------- helpers ----------------
__device__ __forceinline__ float softplusf(float y) {
    return fmaxf(y, 0.0f) + log1pf(expf(-fabsf(y)));
}
__device__ __forceinline__ float warp_sum(float v) {
    for (int o = 16; o; o >>= 1) v += __shfl_down_sync(0xffffffffu, v, o);
    return v;
}

// Two-level inclusive min-scan over 16 registers (24 ops, depth ~28 cy).
// v[15] afterwards = lane total (exact; min associative).
#define LOCAL_CUMMIN16(v) do {                                                     \
    v[1]=fminf(v[1],v[0]);  v[5]=fminf(v[5],v[4]);                                 \
    v[9]=fminf(v[9],v[8]);  v[13]=fminf(v[13],v[12]);                              \
    v[2]=fminf(v[2],v[1]);  v[6]=fminf(v[6],v[5]);                                 \
    v[10]=fminf(v[10],v[9]); v[14]=fminf(v[14],v[13]);                             \
    v[3]=fminf(v[3],v[2]);  v[7]=fminf(v[7],v[6]);                                 \
    v[11]=fminf(v[11],v[10]); v[15]=fminf(v[15],v[14]);                            \
    v[7]=fminf(v[7],v[3]);  v[11]=fminf(v[11],v[7]);  v[15]=fminf(v[15],v[11]);    \
    v[4]=fminf(v[4],v[3]);  v[5]=fminf(v[5],v[3]);  v[6]=fminf(v[6],v[3]);         \
    v[8]=fminf(v[8],v[7]);  v[9]=fminf(v[9],v[7]);  v[10]=fminf(v[10],v[7]);       \
    v[12]=fminf(v[12],v[11]); v[13]=fminf(v[13],v[11]); v[14]=fminf(v[14],v[11]);  \
} while (0)

// Warp exclusive min-scan of per-lane totals. BIG identity at lane 0.
__device__ __forceinline__ float warp_excl_min(float gt, int t) {
    const unsigned full = 0xffffffffu;
    float incl = gt;
    #pragma unroll
    for (int off = 1; off < 32; off <<= 1) {
        float n = __shfl_up_sync(full, incl, off);
        if (t >= off) incl = fminf(incl, n);
    }
    float excl = __shfl_up_sync(full, incl, 1);
    if (t == 0) excl = 3.0e38f;
    return excl;
}

// ---------------- chamfer warp body: 1 warp per sample, 16 cols/thread ----------
// Entire recurrence kept in the scan's shifted domain: p[k] = d[col] - A*col.
// Shifted-domain step costs: up = p+A, ul = p(left)+(B-A), ur = p(right)+(B+A).
// Per-column shift means inter-lane halos need no adjustment.
__device__ void chamfer_body(int b, int t) {
    const float A = 0.955f, INF = 1e6f;
    const float CL = 1.3693f - 0.955f;       // ul add in shifted domain
    const float CR = 1.3693f + 0.955f;       // ur add in shifted domain
    const float LHB = 1e6f + 0.955f;         // halo beyond col -1 (shifted)
    const float RHB = 1e6f - 512.0f * 0.955f;// halo beyond col 512 (shifted)
    const unsigned full = 0xffffffffu;
    float* d = g_d + b * HW;
    const unsigned char* bm = g_bmask + b * HW;
    int hasb = g_hasb[b];

    float ajv[16], ajn[16], iaj[16];
    #pragma unroll
    for (int k = 0; k < 16; k++) {
        ajv[k] = A * (float)(16 * t + k);    // shift of this lane's columns
        ajn[k] = 0.0f - ajv[k];              // seed value in shifted domain
        iaj[k] = INF - ajv[k];               // non-seed value in shifted domain
    }

    float p[16];
    #pragma unroll
    for (int k = 0; k < 16; k++) p[k] = iaj[k];   // row -1 = INF (shifted)
    float lh = LHB, rh = RHB;

    // ---- pass-1 row step (seeds -> shifted output, stored shifted) ----
    #define P1_ROW(RAWREG, ROWI) do {                                              \
        unsigned ws0 = hasb ? (RAWREG).x : ((RAWREG).x >> 1);                      \
        unsigned ws1 = hasb ? (RAWREG).y : ((RAWREG).y >> 1);                      \
        unsigned ws2 = hasb ? (RAWREG).z : ((RAWREG).z >> 1);                      \
        unsigned ws3 = hasb ? (RAWREG).w : ((RAWREG).w >> 1);                      \
        float v[16];                                                               \
        _Pragma("unroll")                                                          \
        for (int k = 0; k < 16; k++) {                                             \
            unsigned w  = (k < 4) ? ws0 : (k < 8) ? ws1 : (k < 12) ? ws2 : ws3;    \
            unsigned sel = (w >> (8 * (k & 3))) & 1u;                              \
            float drow = sel ? ajn[k] : iaj[k];                                    \
            float up = p[k] + A;                                                   \
            float ul = ((k > 0)  ? p[k - 1] : lh) + CL;                            \
            float ur = ((k < 15) ? p[k + 1] : rh) + CR;                            \
            v[k] = fminf(fminf(drow, up), fminf(ul, ur));                          \
        }                                                                          \
        LOCAL_CUMMIN16(v);                                                         \
        float excl = warp_excl_min(v[15], t);                                      \
        _Pragma("unroll")                                                          \
        for (int k = 0; k < 16; k++) p[k] = fminf(v[k], excl);                     \
        lh = __shfl_up_sync(full, p[15], 1);  if (t == 0)  lh = LHB;               \
        rh = __shfl_down_sync(full, p[0], 1); if (t == 31) rh = RHB;               \
        float* row = d + (ROWI) * Ww + t * 16;                                     \
        _Pragma("unroll")                                                          \
        for (int q = 0; q < 4; q++)                                                \
            *(float4*)(row + 4 * q) =                                              \
                make_float4(p[4*q], p[4*q+1], p[4*q+2], p[4*q+3]);                 \
    } while (0)

    // ================= pass 1 (unroll 2, depth-2 prefetch) =================
    {
        uint4 rawA = *(const uint4*)(bm + 0 * Ww + t * 16);
        uint4 rawB = *(const uint4*)(bm + 1 * Ww + t * 16);
        for (int i = 0; i < Hh; i += 2) {
            P1_ROW(rawA, i);
            if (i + 2 < Hh) rawA = *(const uint4*)(bm + (i + 2) * Ww + t * 16);
            P1_ROW(rawB, i + 1);
            if (i + 3 < Hh) rawB = *(const uint4*)(bm + (i + 3) * Ww + t * 16);
        }
    }

    // ================= pass 2: doubly-reversed grid =================
    // Lane t owns reversed cols j' = 16t..16t+15 (orig col 511 - j').
    // Input conversion: stored p1 = d1 - A*origcol; need d1 - A*j' = p1 + conv.
    float conv[16];
    #pragma unroll
    for (int k = 0; k < 16; k++) conv[k] = A * (float)(511 - 2 * (16 * t + k));
    #pragma unroll
    for (int k = 0; k < 16; k++) p[k] = iaj[k];
    lh = LHB; rh = RHB;
    float mx = 0.0f;
    int colbase = 496 - 16 * t;                 // orig col of chunk start (fwd order)

    // orig col (colbase + 4q + e) <-> local k = 15 - 4q - e  (both read AND write)
    #define P2_ROW(FBUF, ROWI) do {                                                \
        float vin[16];                                                             \
        _Pragma("unroll")                                                          \
        for (int q = 0; q < 4; q++) {                                              \
            vin[15 - 4*q - 0] = (FBUF)[q].x + conv[15 - 4*q - 0];                  \
            vin[15 - 4*q - 1] = (FBUF)[q].y + conv[15 - 4*q - 1];                  \
            vin[15 - 4*q - 2] = (FBUF)[q].z + conv[15 - 4*q - 2];                  \
            vin[15 - 4*q - 3] = (FBUF)[q].w + conv[15 - 4*q - 3];                  \
        }                                                                          \
        float v[16];                                                               \
        _Pragma("unroll")                                                          \
        for (int k = 0; k < 16; k++) {                                             \
            float up = p[k] + A;                                                   \
            float ul = ((k > 0)  ? p[k - 1] : lh) + CL;                            \
            float ur = ((k < 15) ? p[k + 1] : rh) + CR;                            \
            v[k] = fminf(fminf(vin[k], up), fminf(ul, ur));                        \
        }                                                                          \
        LOCAL_CUMMIN16(v);                                                         \
        float excl = warp_excl_min(v[15], t);                                      \
        float ab[16];                                                              \
        _Pragma("unroll")                                                          \
        for (int k = 0; k < 16; k++) {                                             \
            p[k] = fminf(v[k], excl);                                              \
            ab[k] = p[k] + ajv[k];                                                 \
            mx = fmaxf(mx, ab[k]);                                                 \
        }                                                                          \
        lh = __shfl_up_sync(full, p[15], 1);  if (t == 0)  lh = LHB;               \
        rh = __shfl_down_sync(full, p[0], 1); if (t == 31) rh = RHB;               \
        float* row = d + (ROWI) * Ww + colbase;                                    \
        _Pragma("unroll")                                                          \
        for (int q = 0; q < 4; q++)                                                \
            *(float4*)(row + 4 * q) =                                              \
                make_float4(ab[15-4*q], ab[15-4*q-1], ab[15-4*q-2], ab[15-4*q-3]); \
    } while (0)

    {
        float4 fA[4], fB[4];
        {
            const float* rA = d + (Hh - 1) * Ww + colbase;
            const float* rB = d + (Hh - 2) * Ww + colbase;
            #pragma unroll
            for (int q = 0; q < 4; q++) { fA[q] = *(const float4*)(rA + 4 * q);
                                          fB[q] = *(const float4*)(rB + 4 * q); }
        }
        for (int i = Hh - 1; i >= 0; i -= 2) {
            P2_ROW(fA, i);
            if (i - 2 >= 0) {
                const float* r = d + (i - 2) * Ww + colbase;
                #pragma unroll
                for (int q = 0; q < 4; q++) fA[q] = *(const float4*)(r + 4 * q);
            }
            P2_ROW(fB, i - 1);
            if (i - 3 >= 0) {
                const float* r = d + (i - 3) * Ww + colbase;
                #pragma unroll
                for (int q = 0; q < 4; q++) fB[q] = *(const float4*)(r + 4 * q);
            }
        }
    }

    #pragma unroll
    for (int o = 16; o; o >>= 1) mx = fmaxf(mx, __shfl_down_sync(full, mx, o));
    if (t == 0) g_dmax[b] = mx;
    #undef P1_ROW
    #undef P2_ROW
}

// ---------------- dist-independent losses + w array (overlapped under chamfer) --
__device__ void loss_nodist_body(int lb, const float* __restrict__ pred,
                                 const int* __restrict__ tgt) {
    int b = lb / LOSS_BLOCKS_PER_B;
    int blk = lb - b * LOSS_BLOCKS_PER_B;
    const float* pb = pred + b * HW;
    const int*   tb = tgt  + b * HW;
    float*       wb = g_w  + b * HW;

    float fs = 0.f, is = 0.f, ps = 0.f, ts = 0.f, ws = 0.f;
    for (int base = blk * 1024 + threadIdx.x * 4; base < HW;
         base += LOSS_BLOCKS_PER_B * 1024) {
        float4 x4 = *(const float4*)(pb + base);
        int4   t4 = *(const int4*)(tb + base);
        float w4[4];
        #pragma unroll
        for (int e = 0; e < 4; e++) {
            float x = (e == 0) ? x4.x : (e == 1) ? x4.y : (e == 2) ? x4.z : x4.w;
            int  ti = (e == 0) ? t4.x : (e == 1) ? t4.y : (e == 2) ? t4.z : t4.w;
            float p  = 1.0f / (1.0f + expf(-x));
            float bce = ti ? softplusf(-x) : softplusf(x);  // -log_sigmoid(+-x)
            float w  = ti ? (1.0f - p) : p;                 // == 1 - pt
            float at = ti ? 0.25f : 0.75f;
            fs += at * w * w * bce;
            ws += w;
            if (ti) { is += p; ts += 1.0f; }
            ps += p;
            w4[e] = w;
        }
        *(float4*)(wb + base) = make_float4(w4[0], w4[1], w4[2], w4[3]);
    }

    __shared__ double acc[5];
    if (threadIdx.x < 5) acc[threadIdx.x] = 0.0;
    __syncthreads();
    fs = warp_sum(fs); is = warp_sum(is); ps = warp_sum(ps);
    ts = warp_sum(ts); ws = warp_sum(ws);
    if ((threadIdx.x & 31) == 0) {
        atomicAdd(&acc[0], (double)fs);
        atomicAdd(&acc[1], (double)is);
        atomicAdd(&acc[2], (double)ps);
        atomicAdd(&acc[3], (double)ts);
        atomicAdd(&acc[4], (double)ws);
    }
    __syncthreads();
    if (threadIdx.x == 0) {
        atomicAdd(&g_focal_acc, acc[0]);
        atomicAdd(&g_inter[b],  acc[1]);
        atomicAdd(&g_sp[b],     acc[2]);
        atomicAdd(&g_st[b],     acc[3]);
        atomicAdd(&g_wsum[b],   acc[4]);
    }
}

// ---------------- fused launch: 16 chamfer blocks + 128 loss blocks ------------
__global__ __launch_bounds__(256) void chamfer_loss_kernel(
        const float* __restrict__ pred, const int* __restrict__ tgt) {
    if (blockIdx.x < Bb) {
        if (threadIdx.x < 32) chamfer_body(blockIdx.x, threadIdx.x);
        return;                                 // no __syncthreads in this branch
    }
    loss_nodist_body(blockIdx.x - Bb, pred, tgt);
}

// ---------------- S2 = sum(w * d) per sample (bnd dist term) ----------------
__global__ void s2_kernel() {
    int b = blockIdx.y;
    const float* wb = g_w + b * HW;
    const float* db = g_d + b * HW;

    float s = 0.f;
    for (int base = blockIdx.x * 1024 + threadIdx.x * 4; base < HW;
         base += gridDim.x * 1024) {
        float4 w4 = *(const float4*)(wb + base);
        float4 d4 = *(const float4*)(db + base);
        s += w4.x * d4.x + w4.y * d4.y + w4.z * d4.z + w4.w * d4.w;
    }

    __shared__ double acc;
    if (threadIdx.x == 0) acc = 0.0;
    __syncthreads();
    s = warp_sum(s);
    if ((threadIdx.x & 31) == 0) atomicAdd(&acc, (double)s);
    __syncthreads();
    if (threadIdx.x == 0) atomicAdd(&g_s2[b], acc);
}

// ---------------- finalize: dice/iou ratios + bnd assembly + weighting ----------
__global__ void final_kernel(const float* __restrict__ lv, float* __restrict__ out) {
    if (threadIdx.x != 0 || blockIdx.x != 0) return;
    double N = (double)TOT;
    double focal = g_focal_acc / N;
    double bnd_sum = 0.0, dsum = 0.0, isum = 0.0;
    for (int b = 0; b < Bb; b++) {
        double inter = g_inter[b];
        double tot   = g_sp[b] + g_st[b];
        dsum += (2.0 * inter + 1e-6) / (tot + 1e-6);
        isum += (inter + 1e-6) / (tot - inter + 1e-6);
        double S1 = g_wsum[b], S2 = g_s2[b];
        if (!g_hasfg[b]) {
            bnd_sum += 2.0 * S1;                 // dist == 1 everywhere
        } else {
            double dmax = (double)g_dmax[b];
            bnd_sum += S1 + (dmax > 0.0 ? S2 / fmax(dmax, 1e-12) : S2);
        }
    }
    double bnd  = bnd_sum / N;
    double dice = 1.0 - dsum / (double)Bb;
    double iou  = 1.0 - isum / (double)Bb;
    double l0 = lv[0], l1 = lv[1], l2 = lv[2], l3 = lv[3];
    double total = exp(-l0) * focal + l0
                 + exp(-l1) * dice  + l1
                 + exp(-l2) * bnd   + l2
                 + exp(-l3) * iou   + l3;
    out[0] = (float)total;
    out[1] = (float)focal;
    out[2] = (float)dice;
    out[3] = (float)bnd;
    out[4] = (float)iou;
}

extern "C" void kernel_launch(void* const* d_in, const int* in_sizes, int n_in,
                              void* d_out, int out_size) {
    const float* pred = (const float*)d_in[0];
    const int*   tgt  = (const int*)d_in[1];
    const float* lv   = (const float*)d_in[2];
    float* out = (float*)d_out;
    (void)in_sizes; (void)n_in; (void)out_size;

    zero_kernel<<<1, 64>>>();
    prep_kernel<<<TOT / 256, 256>>>(tgt);
    chamfer_loss_kernel<<<Bb + NLOSSBLK, 256>>>(pred, tgt);
    s2_kernel<<<dim3(32, Bb), 256>>>();
    final_kernel<<<1, 32>>>(lv, out);
}